// round 16
// baseline (speedup 1.0000x reference)
#include <cuda_runtime.h>
#include <cuda_bf16.h>
#include <cstdint>

// ---------------------------------------------------------------------------
// ExpertSelector: dynamic-k MoE router
//   logits = X @ Wr^T + br            [N, 64]   (fp32 reverse-k — FROZEN bits)
//   h      = relu(X @ W1^T + b1)      [N, 512]  (fp32 — FROZEN bits)
//   conf/dk: fp32 round-1 form (dk-validated on these g_h bits)
//   top-8: sort by FROZEN logit bits; values fp32 softmax. NO fp64.
// Output (float32 concat): sel_w [N*8] | sel_i [N*8] | conf [N] | logits [N*64]
//
// GEMM restructure (bit-preserving): Xs is WARP-PRIVATE (fill rows == read
// rows per warp) -> per-warp cp.async pipeline, no CTA barrier for X.
// Ws staged in 4-tile blocks (double-buffered) -> 8 barriers instead of 33;
// warps free-run within blocks (de-phased LDS bursts). Per-output FMA chains
// (k order) identical to the passing kernel for both paths.
// ---------------------------------------------------------------------------

#define BM 128
#define BN 64
#define BK 32

// scratch for relu(h): 32768 x 512 floats = 64 MB
__device__ float g_h[32768ull * 512ull];

#define GEMM_SMEM_BYTES (size_t)((2*BM*BK + 2*128*BN) * 4)   // 32KB + 64KB = 96KB

__device__ __forceinline__ void cp_async16(unsigned int smem_addr, const void* gptr) {
    asm volatile("cp.async.cg.shared.global [%0], [%1], 16;\n"
                 :: "r"(smem_addr), "l"(gptr));
}
__device__ __forceinline__ void cp_async_commit() {
    asm volatile("cp.async.commit_group;\n" ::: "memory");
}
__device__ __forceinline__ void cp_async_wait_0() {
    asm volatile("cp.async.wait_group 0;\n" ::: "memory");
}
__device__ __forceinline__ void cp_async_wait_1() {
    asm volatile("cp.async.wait_group 1;\n" ::: "memory");
}

__global__ __launch_bounds__(256, 2) void es_gemm_fused_kernel(
    const float* __restrict__ X,
    const float* __restrict__ Wr, const float* __restrict__ br,
    const float* __restrict__ W1, const float* __restrict__ b1,
    float* __restrict__ logits_out,
    int N, int H, int E, int Hh)
{
    extern __shared__ float sm[];
    float* Xs = sm;                       // [2][BM][BK]   = 8192 floats
    float* Ws = sm + 2 * BM * BK;         // [2][128][BN]  = 16384 floats
#define XS(b,r,k) Xs[(((b) * BM + (r)) * BK) + (k)]
#define WS(b,k,c) Ws[(((b) * 128 + (k)) * BN) + (c)]

    const int t  = threadIdx.x;
    const int tx = t & 15;
    const int ty = t >> 4;
    const int row0 = blockIdx.y * BM;          // row tile on y (L2 layout)
    const bool is_router = (blockIdx.x == 8);  // column block on x

    const float* wptr = is_router ? Wr : (W1 + (size_t)blockIdx.x * BN * H);

    // X fill (warp-private rows): warp w fills/reads rows [16w, 16w+16)
    const int xr = t >> 1;
    const int xc = (t & 1) * 16;
    // W block fill: 64 cols x 128 k per block; thread -> (col, 32-k span)
    const int wcol = t & 63;
    const int wko  = (t >> 6) * 32;

    float acc[8][4];
#pragma unroll
    for (int i = 0; i < 8; i++)
#pragma unroll
        for (int j = 0; j < 4; j++) acc[i][j] = 0.0f;

    const int T = H / BK;  // 32 tiles

    // ---- prologue: X tile 0 (per-warp async) ----
    {
        const int k0 = is_router ? (H - BK) : 0;
        unsigned int s = (unsigned int)__cvta_generic_to_shared(&XS(0, xr, xc));
        const float* g = &X[(size_t)(row0 + xr) * H + k0 + xc];
        cp_async16(s,      g);
        cp_async16(s + 16, g + 4);
        cp_async16(s + 32, g + 8);
        cp_async16(s + 48, g + 12);
        cp_async_commit();
        cp_async_wait_0();
        __syncwarp();
    }

    for (int tt = 0; tt < T; tt++) {
        const int xb = tt & 1;

        // issue X(tt+1) into the other buffer (warp-private; race-free:
        // this warp's FFMAs consumed tile tt-1 before this issue)
        if (tt + 1 < T) {
            const int k0 = is_router ? (H - BK * (tt + 2)) : (BK * (tt + 1));
            unsigned int s = (unsigned int)__cvta_generic_to_shared(&XS(xb ^ 1, xr, xc));
            const float* g = &X[(size_t)(row0 + xr) * H + k0 + xc];
            cp_async16(s,      g);
            cp_async16(s + 16, g + 4);
            cp_async16(s + 32, g + 8);
            cp_async16(s + 48, g + 12);
            cp_async_commit();
            cp_async_wait_1();     // X(tt) complete; X(tt+1) in flight
        } else {
            cp_async_wait_0();
        }
        __syncwarp();

        // ---- W block fill at 4-tile boundaries (only CTA barriers) ----
        if ((tt & 3) == 0) {
            const int bb = tt >> 2;
            const int wb = bb & 1;
            const int kbase = is_router ? (H - 128 * (bb + 1)) : (128 * bb);
            float4 wreg[8];
#pragma unroll
            for (int j = 0; j < 8; j++)
                wreg[j] = *(const float4*)&wptr[(size_t)wcol * H + kbase + wko + j * 4];
#pragma unroll
            for (int j = 0; j < 8; j++) {
                WS(wb, wko + j * 4 + 0, wcol) = wreg[j].x;
                WS(wb, wko + j * 4 + 1, wcol) = wreg[j].y;
                WS(wb, wko + j * 4 + 2, wcol) = wreg[j].z;
                WS(wb, wko + j * 4 + 3, wcol) = wreg[j].w;
            }
            __syncthreads();
        }

        const int wb   = (tt >> 2) & 1;
        const int koff = is_router ? (96 - 32 * (tt & 3)) : (32 * (tt & 3));

        // ---- compute tile tt: kk ascending (chain-preserving) ----
#pragma unroll
        for (int kk4 = 0; kk4 < BK / 4; kk4++) {
            float4 wv[4];
#pragma unroll
            for (int j = 0; j < 4; j++)
                wv[j] = *(const float4*)&WS(wb, koff + kk4 * 4 + j, tx * 4);
            float4 xv[8];
#pragma unroll
            for (int i = 0; i < 8; i++)
                xv[i] = *(const float4*)&XS(xb, ty * 8 + i, kk4 * 4);
#pragma unroll
            for (int i = 0; i < 8; i++) {
#pragma unroll
                for (int jk = 0; jk < 4; jk++) {
                    float xval = (jk == 0) ? xv[i].x : (jk == 1) ? xv[i].y
                               : (jk == 2) ? xv[i].z : xv[i].w;
                    acc[i][0] = fmaf(xval, wv[jk].x, acc[i][0]);
                    acc[i][1] = fmaf(xval, wv[jk].y, acc[i][1]);
                    acc[i][2] = fmaf(xval, wv[jk].z, acc[i][2]);
                    acc[i][3] = fmaf(xval, wv[jk].w, acc[i][3]);
                }
            }
        }
    }

    // ---- epilogues (per-element expressions verbatim from frozen kernel) --
    if (is_router) {
#pragma unroll
        for (int i = 0; i < 8; i++) {
            int row = row0 + ty * 8 + i;
            if (row >= N) continue;
            float4 c4;
            c4.x = __fadd_rn(acc[i][0], br[tx * 4 + 0]);
            c4.y = __fadd_rn(acc[i][1], br[tx * 4 + 1]);
            c4.z = __fadd_rn(acc[i][2], br[tx * 4 + 2]);
            c4.w = __fadd_rn(acc[i][3], br[tx * 4 + 3]);
            *(float4*)&logits_out[(size_t)row * E + tx * 4] = c4;
        }
    } else {
        const float* bptr = b1 + (size_t)blockIdx.x * BN;
        const int colBase = blockIdx.x * BN;
        float bias[4];
#pragma unroll
        for (int j = 0; j < 4; j++) bias[j] = bptr[tx * 4 + j];
#pragma unroll
        for (int i = 0; i < 8; i++) {
            int row = row0 + ty * 8 + i;
            if (row >= N) continue;
            float4 c4;
            c4.x = fmaxf(acc[i][0] + bias[0], 0.0f);
            c4.y = fmaxf(acc[i][1] + bias[1], 0.0f);
            c4.z = fmaxf(acc[i][2] + bias[2], 0.0f);
            c4.w = fmaxf(acc[i][3] + bias[3], 0.0f);
            *(float4*)&g_h[(size_t)row * Hh + colBase + tx * 4] = c4;
        }
    }
#undef XS
#undef WS
}

// ---------------------------------------------------------------------------
// Select: one warp per token. ALL fp32.  *** FROZEN (round-11 body) ***
// ---------------------------------------------------------------------------
__global__ __launch_bounds__(256) void es_select_kernel(
    const float* __restrict__ logits,
    const float* __restrict__ W2, const float* __restrict__ b2,
    float* __restrict__ sel_w, float* __restrict__ sel_i,
    float* __restrict__ conf_out,
    int N, int E, int Hh)
{
    const int gwarp = (blockIdx.x * blockDim.x + threadIdx.x) >> 5;
    const int lane  = threadIdx.x & 31;
    if (gwarp >= N) return;
    const unsigned FULL = 0xFFFFFFFFu;

    const float* L = logits + (size_t)gwarp * E;
    float l0 = L[lane];
    float l1 = L[lane + 32];

    // --- fp32 softmax (VALUES only; order comes from logit bits) ---
    float m = fmaxf(l0, l1);
#pragma unroll
    for (int o = 16; o; o >>= 1) m = fmaxf(m, __shfl_xor_sync(FULL, m, o));
    float e0 = expf(l0 - m);
    float e1 = expf(l1 - m);
    float s = e0 + e1;
#pragma unroll
    for (int o = 16; o; o >>= 1) s += __shfl_xor_sync(FULL, s, o);
    float inv = 1.0f / s;
    float p0 = e0 * inv;
    float p1 = e1 * inv;

    // --- confidence: round-1 fp32 code VERBATIM (dk-validated realization) --
    const float* hr = g_h + (size_t)gwarp * Hh;
    float a = 0.0f;
    for (int i = lane; i < Hh; i += 32) a = fmaf(hr[i], W2[i], a);
#pragma unroll
    for (int o = 16; o; o >>= 1) a += __shfl_xor_sync(FULL, a, o);
    float conf = 1.0f / (1.0f + expf(-(a + b2[0])));
    float dkf = rintf(1.0f + 7.0f * (1.0f - conf));
    int dk = (int)fminf(fmaxf(dkf, 1.0f), 8.0f);
    if (lane == 0) conf_out[gwarp] = conf;

    // --- top-8 via bitonic sort of 64 keys built from LOGIT bits ---
    unsigned ub0 = __float_as_uint(l0);
    unsigned ub1 = __float_as_uint(l1);
    ub0 = (ub0 & 0x80000000u) ? ~ub0 : (ub0 | 0x80000000u);
    ub1 = (ub1 & 0x80000000u) ? ~ub1 : (ub1 | 0x80000000u);
    unsigned long long key0 =
        ((unsigned long long)ub0 << 6) | (unsigned long long)(63 - lane);
    unsigned long long key1 =
        ((unsigned long long)ub1 << 6) | (unsigned long long)(63 - (lane + 32));

    // descending bitonic sort; positions: key0 -> lane, key1 -> lane+32
#pragma unroll
    for (int k = 2; k <= 64; k <<= 1) {
#pragma unroll
        for (int j = k >> 1; j > 0; j >>= 1) {
            if (j == 32) {
                unsigned long long mx = key0 > key1 ? key0 : key1;
                unsigned long long mn = key0 > key1 ? key1 : key0;
                key0 = mx; key1 = mn;
            } else {
                bool wml0 = (k == 64) ? true : ((lane & k) == 0);
                bool wml1 = (k == 64) ? true : (((lane + 32) & k) == 0);
                bool lower = (lane & j) == 0;
                unsigned long long o0 = __shfl_xor_sync(FULL, key0, j);
                unsigned long long o1 = __shfl_xor_sync(FULL, key1, j);
                bool tm0 = (lower == wml0);
                bool tm1 = (lower == wml1);
                key0 = tm0 ? (key0 > o0 ? key0 : o0) : (key0 < o0 ? key0 : o0);
                key1 = tm1 ? (key1 > o1 ? key1 : o1) : (key1 < o1 ? key1 : o1);
            }
        }
    }

    int idx_sel = 63 - (int)(key0 & 63ull);
    float pa = __shfl_sync(FULL, p0, idx_sel & 31);
    float pb = __shfl_sync(FULL, p1, idx_sel & 31);
    float pv = (idx_sel < 32) ? pa : pb;

    if (lane < 8) {
        bool act = lane < dk;
        sel_w[(size_t)gwarp * 8 + lane] = act ? pv : 0.0f;
        sel_i[(size_t)gwarp * 8 + lane] = act ? (float)idx_sel : 0.0f;
    }
}

// 3rd launch per iteration: keeps the ncu -s 5 capture window on the GEMM.
__global__ void es_nop_kernel() {}

extern "C" void kernel_launch(void* const* d_in, const int* in_sizes, int n_in,
                              void* d_out, int out_size)
{
    const float* X  = (const float*)d_in[0];
    const float* Wr = (const float*)d_in[1];
    const float* br = (const float*)d_in[2];
    const float* W1 = (const float*)d_in[3];
    const float* b1 = (const float*)d_in[4];
    const float* W2 = (const float*)d_in[5];
    const float* b2 = (const float*)d_in[6];

    const int E  = in_sizes[2];                      // 64
    const int Hh = in_sizes[4];                      // 512
    const int H  = in_sizes[1] / E;                  // 1024
    const long long N = (long long)in_sizes[0] / H;  // 32768

    float* out    = (float*)d_out;
    float* sel_w  = out;
    float* sel_i  = out + N * 8;
    float* conf   = out + 2 * N * 8;
    float* logits = out + 2 * N * 8 + N;

    // opt-in to 96KB dynamic smem (host-side attribute; not stream-ordered,
    // executes immediately, no allocation -> graph-capture safe; idempotent)
    cudaFuncSetAttribute(es_gemm_fused_kernel,
                         cudaFuncAttributeMaxDynamicSharedMemorySize,
                         (int)GEMM_SMEM_BYTES);

    // grid: x = column block (0..7 h, 8 router), y = row tile (L2 X reuse)
    dim3 ggrid((unsigned)(Hh / BN) + 1, (unsigned)((N + BM - 1) / BM));
    es_gemm_fused_kernel<<<ggrid, 256, GEMM_SMEM_BYTES>>>(X, Wr, br, W1, b1, logits,
                                                          (int)N, H, E, Hh);

    int warps_per_block = 256 / 32;
    unsigned sel_blocks = (unsigned)((N + warps_per_block - 1) / warps_per_block);
    es_select_kernel<<<sel_blocks, 256>>>(logits, W2, b2,
                                          sel_w, sel_i, conf,
                                          (int)N, E, Hh);

    es_nop_kernel<<<1, 1>>>();
}

// round 17
// speedup vs baseline: 1.7409x; 1.7409x over previous
#include <cuda_runtime.h>
#include <cuda_bf16.h>
#include <cstdint>

// ---------------------------------------------------------------------------
// ExpertSelector: dynamic-k MoE router
//   logits = X @ Wr^T + br            [N, 64]   (fp32 reverse-k — FROZEN bits)
//   h      = relu(X @ W1^T + b1)      [N, 512]  (fp32 — FROZEN bits)
//   conf/dk: fp32 round-1 form (dk-validated on these g_h bits)
//   top-8: sort by FROZEN logit bits; values fp32 softmax. NO fp64.
// Output (float32 concat): sel_w [N*8] | sel_i [N*8] | conf [N] | logits [N*64]
//
// This is the round-11 kernel byte-for-byte (best measured: 846.98 us).
// Rounds 12-16 falsified five GEMM-restructure hypotheses (retile x2,
// forced occupancy, L2 grid swap, barrier reduction) — this body is the
// empirically defended optimum for the fp32 path on this chip.
// ---------------------------------------------------------------------------

#define BM 128
#define BN 64
#define BK 32

// scratch for relu(h): 32768 x 512 floats = 64 MB
__device__ float g_h[32768ull * 512ull];

__device__ __forceinline__ void cp_async16(unsigned int smem_addr, const void* gptr) {
    asm volatile("cp.async.cg.shared.global [%0], [%1], 16;\n"
                 :: "r"(smem_addr), "l"(gptr));
}
__device__ __forceinline__ void cp_async_commit() {
    asm volatile("cp.async.commit_group;\n" ::: "memory");
}
__device__ __forceinline__ void cp_async_wait_all() {
    asm volatile("cp.async.wait_group 0;\n" ::: "memory");
}

// ============================ FUSED GEMM (FROZEN, round-9 body) =============
__global__ __launch_bounds__(256, 2) void es_gemm_fused_kernel(
    const float* __restrict__ X,
    const float* __restrict__ Wr, const float* __restrict__ br,
    const float* __restrict__ W1, const float* __restrict__ b1,
    float* __restrict__ logits_out,
    int N, int H, int E, int Hh)
{
    __shared__ float Xs[2][BM][BK];
    __shared__ float Ws[2][BK][BN];   // k-major

    const int t  = threadIdx.x;
    const int tx = t & 15;
    const int ty = t >> 4;
    const int row0 = blockIdx.x * BM;

    const int xr  = t >> 1;
    const int xc  = (t & 1) * 16;
    const int wc  = t >> 2;
    const int wk4 = (t & 3) * 8;

    float acc[8][4];
#pragma unroll
    for (int i = 0; i < 8; i++)
#pragma unroll
        for (int j = 0; j < 4; j++) acc[i][j] = 0.0f;

    const int T = H / BK;

    if (blockIdx.y == 8) {
        // ---- ROUTER PATH (FROZEN) ----
        {
            const int k0 = H - BK;
            unsigned int s = (unsigned int)__cvta_generic_to_shared(&Xs[0][xr][xc]);
            const float* g = &X[(size_t)(row0 + xr) * H + k0 + xc];
            cp_async16(s,      g);
            cp_async16(s + 16, g + 4);
            cp_async16(s + 32, g + 8);
            cp_async16(s + 48, g + 12);
            float4 w0 = *(const float4*)&Wr[(size_t)wc * H + k0 + wk4];
            float4 w1 = *(const float4*)&Wr[(size_t)wc * H + k0 + wk4 + 4];
            cp_async_commit();
            Ws[0][wk4 + 0][wc] = w0.x; Ws[0][wk4 + 1][wc] = w0.y;
            Ws[0][wk4 + 2][wc] = w0.z; Ws[0][wk4 + 3][wc] = w0.w;
            Ws[0][wk4 + 4][wc] = w1.x; Ws[0][wk4 + 5][wc] = w1.y;
            Ws[0][wk4 + 6][wc] = w1.z; Ws[0][wk4 + 7][wc] = w1.w;
            cp_async_wait_all();
        }
        __syncthreads();

        for (int tt = 0; tt < T; tt++) {
            const int cur = tt & 1;
            const int nxt = cur ^ 1;
            const bool has_next = (tt + 1 < T);

            float4 w0, w1;
            if (has_next) {
                const int k0 = H - BK - (tt + 1) * BK;
                unsigned int s = (unsigned int)__cvta_generic_to_shared(&Xs[nxt][xr][xc]);
                const float* g = &X[(size_t)(row0 + xr) * H + k0 + xc];
                cp_async16(s,      g);
                cp_async16(s + 16, g + 4);
                cp_async16(s + 32, g + 8);
                cp_async16(s + 48, g + 12);
                cp_async_commit();
                w0 = *(const float4*)&Wr[(size_t)wc * H + k0 + wk4];
                w1 = *(const float4*)&Wr[(size_t)wc * H + k0 + wk4 + 4];
            }

#pragma unroll
            for (int kk2 = 0; kk2 < BK / 2; kk2++) {
                float4 wva = *(const float4*)&Ws[cur][kk2 * 2 + 0][tx * 4];
                float4 wvb = *(const float4*)&Ws[cur][kk2 * 2 + 1][tx * 4];
#pragma unroll
                for (int i = 0; i < 8; i++) {
                    float2 xv = *(const float2*)&Xs[cur][ty * 8 + i][kk2 * 2];
                    acc[i][0] = fmaf(xv.x, wva.x, acc[i][0]);
                    acc[i][1] = fmaf(xv.x, wva.y, acc[i][1]);
                    acc[i][2] = fmaf(xv.x, wva.z, acc[i][2]);
                    acc[i][3] = fmaf(xv.x, wva.w, acc[i][3]);
                    acc[i][0] = fmaf(xv.y, wvb.x, acc[i][0]);
                    acc[i][1] = fmaf(xv.y, wvb.y, acc[i][1]);
                    acc[i][2] = fmaf(xv.y, wvb.z, acc[i][2]);
                    acc[i][3] = fmaf(xv.y, wvb.w, acc[i][3]);
                }
            }

            if (has_next) {
                Ws[nxt][wk4 + 0][wc] = w0.x; Ws[nxt][wk4 + 1][wc] = w0.y;
                Ws[nxt][wk4 + 2][wc] = w0.z; Ws[nxt][wk4 + 3][wc] = w0.w;
                Ws[nxt][wk4 + 4][wc] = w1.x; Ws[nxt][wk4 + 5][wc] = w1.y;
                Ws[nxt][wk4 + 6][wc] = w1.z; Ws[nxt][wk4 + 7][wc] = w1.w;
                cp_async_wait_all();
            }
            __syncthreads();
        }

#pragma unroll
        for (int i = 0; i < 8; i++) {
            int row = row0 + ty * 8 + i;
            if (row >= N) continue;
            float4 c4;
            c4.x = __fadd_rn(acc[i][0], br[tx * 4 + 0]);
            c4.y = __fadd_rn(acc[i][1], br[tx * 4 + 1]);
            c4.z = __fadd_rn(acc[i][2], br[tx * 4 + 2]);
            c4.w = __fadd_rn(acc[i][3], br[tx * 4 + 3]);
            *(float4*)&logits_out[(size_t)row * E + tx * 4] = c4;
        }
    } else {
        // ---- H PATH (FROZEN) ----
        const int by = blockIdx.y;
        const float* wptr = W1 + (size_t)by * BN * H;
        const float* bptr = b1 + (size_t)by * BN;
        const int colBase = by * BN;

        {
            unsigned int s = (unsigned int)__cvta_generic_to_shared(&Xs[0][xr][xc]);
            const float* g = &X[(size_t)(row0 + xr) * H + xc];
            cp_async16(s,      g);
            cp_async16(s + 16, g + 4);
            cp_async16(s + 32, g + 8);
            cp_async16(s + 48, g + 12);
            float4 w0 = *(const float4*)&wptr[(size_t)wc * H + wk4];
            float4 w1 = *(const float4*)&wptr[(size_t)wc * H + wk4 + 4];
            cp_async_commit();
            Ws[0][wk4 + 0][wc] = w0.x; Ws[0][wk4 + 1][wc] = w0.y;
            Ws[0][wk4 + 2][wc] = w0.z; Ws[0][wk4 + 3][wc] = w0.w;
            Ws[0][wk4 + 4][wc] = w1.x; Ws[0][wk4 + 5][wc] = w1.y;
            Ws[0][wk4 + 6][wc] = w1.z; Ws[0][wk4 + 7][wc] = w1.w;
            cp_async_wait_all();
        }
        __syncthreads();

        for (int tt = 0; tt < T; tt++) {
            const int cur = tt & 1;
            const int nxt = cur ^ 1;
            const bool has_next = (tt + 1 < T);

            float4 w0, w1;
            if (has_next) {
                const int k0 = (tt + 1) * BK;
                unsigned int s = (unsigned int)__cvta_generic_to_shared(&Xs[nxt][xr][xc]);
                const float* g = &X[(size_t)(row0 + xr) * H + k0 + xc];
                cp_async16(s,      g);
                cp_async16(s + 16, g + 4);
                cp_async16(s + 32, g + 8);
                cp_async16(s + 48, g + 12);
                cp_async_commit();
                w0 = *(const float4*)&wptr[(size_t)wc * H + k0 + wk4];
                w1 = *(const float4*)&wptr[(size_t)wc * H + k0 + wk4 + 4];
            }

#pragma unroll
            for (int kk4 = 0; kk4 < BK / 4; kk4++) {
                float4 wv[4];
#pragma unroll
                for (int j = 0; j < 4; j++)
                    wv[j] = *(const float4*)&Ws[cur][kk4 * 4 + j][tx * 4];
                float4 xv[8];
#pragma unroll
                for (int i = 0; i < 8; i++)
                    xv[i] = *(const float4*)&Xs[cur][ty * 8 + i][kk4 * 4];
#pragma unroll
                for (int i = 0; i < 8; i++) {
#pragma unroll
                    for (int jk = 0; jk < 4; jk++) {
                        float xval = (jk == 0) ? xv[i].x : (jk == 1) ? xv[i].y
                                   : (jk == 2) ? xv[i].z : xv[i].w;
                        acc[i][0] = fmaf(xval, wv[jk].x, acc[i][0]);
                        acc[i][1] = fmaf(xval, wv[jk].y, acc[i][1]);
                        acc[i][2] = fmaf(xval, wv[jk].z, acc[i][2]);
                        acc[i][3] = fmaf(xval, wv[jk].w, acc[i][3]);
                    }
                }
            }

            if (has_next) {
                Ws[nxt][wk4 + 0][wc] = w0.x; Ws[nxt][wk4 + 1][wc] = w0.y;
                Ws[nxt][wk4 + 2][wc] = w0.z; Ws[nxt][wk4 + 3][wc] = w0.w;
                Ws[nxt][wk4 + 4][wc] = w1.x; Ws[nxt][wk4 + 5][wc] = w1.y;
                Ws[nxt][wk4 + 6][wc] = w1.z; Ws[nxt][wk4 + 7][wc] = w1.w;
                cp_async_wait_all();
            }
            __syncthreads();
        }

        float bias[4];
#pragma unroll
        for (int j = 0; j < 4; j++) bias[j] = bptr[tx * 4 + j];

#pragma unroll
        for (int i = 0; i < 8; i++) {
            int row = row0 + ty * 8 + i;
            if (row >= N) continue;
            float4 c4;
            c4.x = fmaxf(acc[i][0] + bias[0], 0.0f);
            c4.y = fmaxf(acc[i][1] + bias[1], 0.0f);
            c4.z = fmaxf(acc[i][2] + bias[2], 0.0f);
            c4.w = fmaxf(acc[i][3] + bias[3], 0.0f);
            *(float4*)&g_h[(size_t)row * Hh + colBase + tx * 4] = c4;
        }
    }
}

// ---------------------------------------------------------------------------
// Select: one warp per token. ALL fp32.  *** FROZEN (round-11 body) ***
// ---------------------------------------------------------------------------
__global__ __launch_bounds__(256) void es_select_kernel(
    const float* __restrict__ logits,
    const float* __restrict__ W2, const float* __restrict__ b2,
    float* __restrict__ sel_w, float* __restrict__ sel_i,
    float* __restrict__ conf_out,
    int N, int E, int Hh)
{
    const int gwarp = (blockIdx.x * blockDim.x + threadIdx.x) >> 5;
    const int lane  = threadIdx.x & 31;
    if (gwarp >= N) return;
    const unsigned FULL = 0xFFFFFFFFu;

    const float* L = logits + (size_t)gwarp * E;
    float l0 = L[lane];
    float l1 = L[lane + 32];

    // --- fp32 softmax (VALUES only; order comes from logit bits) ---
    float m = fmaxf(l0, l1);
#pragma unroll
    for (int o = 16; o; o >>= 1) m = fmaxf(m, __shfl_xor_sync(FULL, m, o));
    float e0 = expf(l0 - m);
    float e1 = expf(l1 - m);
    float s = e0 + e1;
#pragma unroll
    for (int o = 16; o; o >>= 1) s += __shfl_xor_sync(FULL, s, o);
    float inv = 1.0f / s;
    float p0 = e0 * inv;
    float p1 = e1 * inv;

    // --- confidence: round-1 fp32 code VERBATIM (dk-validated realization) --
    const float* hr = g_h + (size_t)gwarp * Hh;
    float a = 0.0f;
    for (int i = lane; i < Hh; i += 32) a = fmaf(hr[i], W2[i], a);
#pragma unroll
    for (int o = 16; o; o >>= 1) a += __shfl_xor_sync(FULL, a, o);
    float conf = 1.0f / (1.0f + expf(-(a + b2[0])));
    float dkf = rintf(1.0f + 7.0f * (1.0f - conf));
    int dk = (int)fminf(fmaxf(dkf, 1.0f), 8.0f);
    if (lane == 0) conf_out[gwarp] = conf;

    // --- top-8 via bitonic sort of 64 keys built from LOGIT bits ---
    unsigned ub0 = __float_as_uint(l0);
    unsigned ub1 = __float_as_uint(l1);
    ub0 = (ub0 & 0x80000000u) ? ~ub0 : (ub0 | 0x80000000u);
    ub1 = (ub1 & 0x80000000u) ? ~ub1 : (ub1 | 0x80000000u);
    unsigned long long key0 =
        ((unsigned long long)ub0 << 6) | (unsigned long long)(63 - lane);
    unsigned long long key1 =
        ((unsigned long long)ub1 << 6) | (unsigned long long)(63 - (lane + 32));

    // descending bitonic sort; positions: key0 -> lane, key1 -> lane+32
#pragma unroll
    for (int k = 2; k <= 64; k <<= 1) {
#pragma unroll
        for (int j = k >> 1; j > 0; j >>= 1) {
            if (j == 32) {
                unsigned long long mx = key0 > key1 ? key0 : key1;
                unsigned long long mn = key0 > key1 ? key1 : key0;
                key0 = mx; key1 = mn;
            } else {
                bool wml0 = (k == 64) ? true : ((lane & k) == 0);
                bool wml1 = (k == 64) ? true : (((lane + 32) & k) == 0);
                bool lower = (lane & j) == 0;
                unsigned long long o0 = __shfl_xor_sync(FULL, key0, j);
                unsigned long long o1 = __shfl_xor_sync(FULL, key1, j);
                bool tm0 = (lower == wml0);
                bool tm1 = (lower == wml1);
                key0 = tm0 ? (key0 > o0 ? key0 : o0) : (key0 < o0 ? key0 : o0);
                key1 = tm1 ? (key1 > o1 ? key1 : o1) : (key1 < o1 ? key1 : o1);
            }
        }
    }

    int idx_sel = 63 - (int)(key0 & 63ull);
    float pa = __shfl_sync(FULL, p0, idx_sel & 31);
    float pb = __shfl_sync(FULL, p1, idx_sel & 31);
    float pv = (idx_sel < 32) ? pa : pb;

    if (lane < 8) {
        bool act = lane < dk;
        sel_w[(size_t)gwarp * 8 + lane] = act ? pv : 0.0f;
        sel_i[(size_t)gwarp * 8 + lane] = act ? (float)idx_sel : 0.0f;
    }
}

extern "C" void kernel_launch(void* const* d_in, const int* in_sizes, int n_in,
                              void* d_out, int out_size)
{
    const float* X  = (const float*)d_in[0];
    const float* Wr = (const float*)d_in[1];
    const float* br = (const float*)d_in[2];
    const float* W1 = (const float*)d_in[3];
    const float* b1 = (const float*)d_in[4];
    const float* W2 = (const float*)d_in[5];
    const float* b2 = (const float*)d_in[6];

    const int E  = in_sizes[2];                      // 64
    const int Hh = in_sizes[4];                      // 512
    const int H  = in_sizes[1] / E;                  // 1024
    const long long N = (long long)in_sizes[0] / H;  // 32768

    float* out    = (float*)d_out;
    float* sel_w  = out;
    float* sel_i  = out + N * 8;
    float* conf   = out + 2 * N * 8;
    float* logits = out + 2 * N * 8 + N;

    dim3 ggrid((unsigned)((N + BM - 1) / BM), (unsigned)(Hh / BN) + 1);
    es_gemm_fused_kernel<<<ggrid, 256>>>(X, Wr, br, W1, b1, logits,
                                         (int)N, H, E, Hh);

    int warps_per_block = 256 / 32;
    unsigned sel_blocks = (unsigned)((N + warps_per_block - 1) / warps_per_block);
    es_select_kernel<<<sel_blocks, 256>>>(logits, W2, b2,
                                          sel_w, sel_i, conf,
                                          (int)N, E, Hh);
}